// round 11
// baseline (speedup 1.0000x reference)
#include <cuda_runtime.h>
#include <cuda_bf16.h>

#define K_BONES 512
#define NCHUNK  (K_BONES / 8)          // 64 chunks of 8 bones
#define SCALE   28.853900817779268f    // SIGMA * log2(e), SIGMA = 20

typedef unsigned long long u64;
typedef unsigned int u32;

// ---- packed f32x2 helpers (sm_100a) ---------------------------------------
__device__ __forceinline__ u64 pk2(float lo, float hi) {
    u64 r;
    asm("mov.b64 %0, {%1, %2};" : "=l"(r) : "f"(lo), "f"(hi));
    return r;
}
__device__ __forceinline__ void upk2(u64 v, float& lo, float& hi) {
    asm("mov.b64 {%0, %1}, %2;" : "=f"(lo), "=f"(hi) : "l"(v));
}
__device__ __forceinline__ u64 addx2(u64 a, u64 b) {
    u64 r;
    asm("add.rn.f32x2 %0, %1, %2;" : "=l"(r) : "l"(a), "l"(b));
    return r;
}
__device__ __forceinline__ u64 fmax2(u64 a, u64 b, u64 c) {
    u64 r;
    asm("fma.rn.f32x2 %0, %1, %2, %3;" : "=l"(r) : "l"(a), "l"(b), "l"(c));
    return r;
}

// e = ex2(-sqrt(max(d2,0))) -> tf32 bits
__device__ __forceinline__ u32 weight_tf32(float d2) {
    d2 = fmaxf(d2, 0.0f);
    float r, e;
    asm("sqrt.approx.f32 %0, %1;" : "=f"(r) : "f"(d2));
    asm("ex2.approx.f32 %0, %1;" : "=f"(e) : "f"(-r));
    u32 t;
    asm("cvt.rna.tf32.f32 %0, %1;" : "=r"(t) : "f"(e));
    return t;
}

__device__ __forceinline__ u32 tf32_of(float v) {
    u32 t;
    asm("cvt.rna.tf32.f32 %0, %1;" : "=r"(t) : "f"(v));
    return t;
}

// m16n8k8 row.col tf32 MMA, C += A*B
__device__ __forceinline__ void mma8(float& c0, float& c1, float& c2, float& c3,
                                     u32 a0, u32 a1, u32 a2, u32 a3,
                                     u32 b0, u32 b1) {
    asm("mma.sync.aligned.m16n8k8.row.col.f32.tf32.tf32.f32 "
        "{%0,%1,%2,%3}, {%4,%5,%6,%7}, {%8,%9}, {%0,%1,%2,%3};"
        : "+f"(c0), "+f"(c1), "+f"(c2), "+f"(c3)
        : "r"(a0), "r"(a1), "r"(a2), "r"(a3), "r"(b0), "r"(b1));
}

// ---------------------------------------------------------------------------
// Single fused kernel. Per block: 128 threads (4 warps), 64 points.
//  1) Inline bone prep: Gram-Schmidt all 512 bones into smem:
//     - loc table, pair-packed over (tg, tg+4) within each 8-bone chunk
//     - B matrix [512 x 16] tf32: cols 0-11 = rows of [R - I | t],
//       col 12 = 1 (softmax denominator via the MMA), cols 13-15 = 0;
//       stored pair-packed (B[k], B[k+4]) for direct b-fragment loads.
//  2) Mainloop over 64 chunks: each thread computes its 4 A-fragment
//     weights e = ex2(-sqrt(d2)) IN REGISTERS (fragment-native, no smem
//     transit), then 2 tf32 MMAs accumulate C[16 points x 16 cols].
//  3) Epilogue: C -> smem (1KB/warp), 16 lanes apply delta form:
//     out = p + (D . (x,y,z,1)) / s.
// Delta form keeps tf32 rounding ~1e-5 absolute on the output.
// ---------------------------------------------------------------------------
__global__ __launch_bounds__(128, 5)
void skin_mma_kernel(const float* __restrict__ xyz,
                     const float* __restrict__ bone_locs,
                     const float* __restrict__ bone_transf,
                     const int* __restrict__ tidx_p,
                     float* __restrict__ out, int n) {
    __shared__ float s_locp[NCHUNK * 4 * 8];        // 8 KB
    __shared__ float s_B[NCHUNK * 4 * 16 * 2];      // 32 KB (tf32 bits as float)
    __shared__ float s_ep[4][16][17];               // 4.25 KB epilogue scratch

    // ---------------- inline bone prep ----------------
    {
        int t = tidx_p[0];
        float S2 = SCALE * SCALE;
        for (int k = threadIdx.x; k < K_BONES; k += 128) {
            const float* p = bone_transf + ((long long)t * K_BONES + k) * 9;

            float a1x = p[0], a2x = p[1];
            float a1y = p[2], a2y = p[3];
            float a1z = p[4], a2z = p[5];

            float n1 = sqrtf(a1x * a1x + a1y * a1y + a1z * a1z) + 1e-12f;
            float b1x = a1x / n1, b1y = a1y / n1, b1z = a1z / n1;

            float d = b1x * a2x + b1y * a2y + b1z * a2z;
            float cx = a2x - d * b1x, cy = a2y - d * b1y, cz = a2z - d * b1z;
            float n2 = sqrtf(cx * cx + cy * cy + cz * cz) + 1e-12f;
            float b2x = cx / n2, b2y = cy / n2, b2z = cz / n2;

            float b3x = b1y * b2z - b1z * b2y;
            float b3y = b1z * b2x - b1x * b2z;
            float b3z = b1x * b2y - b1y * b2x;

            float bx = bone_locs[3 * k + 0];
            float by = bone_locs[3 * k + 1];
            float bz = bone_locs[3 * k + 2];

            int c = k >> 3, w = k & 7, tg = w & 3, half = w >> 2;

            float* lp = s_locp + (c * 4 + tg) * 8;
            lp[0 * 2 + half] = -2.0f * S2 * bx;
            lp[1 * 2 + half] = -2.0f * S2 * by;
            lp[2 * 2 + half] = -2.0f * S2 * bz;
            lp[3 * 2 + half] = S2 * (bx * bx + by * by + bz * bz);

            // delta-form B row: [R - I | t] rows + ones column
            float Brow[16] = {b1x - 1.0f, b2x, b3x, p[6],
                              b1y, b2y - 1.0f, b3y, p[7],
                              b1z, b2z, b3z - 1.0f, p[8],
                              1.0f, 0.0f, 0.0f, 0.0f};
            float* bdst = s_B + (c * 4 + tg) * 32;
            #pragma unroll
            for (int j = 0; j < 16; j++)
                bdst[j * 2 + half] = __uint_as_float(tf32_of(Brow[j]));
        }
    }
    __syncthreads();

    // ---------------- mainloop ----------------
    int lane = threadIdx.x & 31;
    int warp = threadIdx.x >> 5;
    int g = lane >> 2;          // point-group 0..7
    int tg = lane & 3;          // bone-thread 0..3
    int pbase = blockIdx.x * 64 + warp * 16;

    int i0 = pbase + g;
    int i1 = i0 + 8;
    int j0 = i0 < n ? i0 : (n - 1);
    int j1 = i1 < n ? i1 : (n - 1);
    float x0 = xyz[3 * j0], y0 = xyz[3 * j0 + 1], z0 = xyz[3 * j0 + 2];
    float x1 = xyz[3 * j1], y1 = xyz[3 * j1 + 1], z1 = xyz[3 * j1 + 2];

    float S2 = SCALE * SCALE;
    u64 xd0 = pk2(x0, x0), yd0 = pk2(y0, y0), zd0 = pk2(z0, z0);
    u64 xd1 = pk2(x1, x1), yd1 = pk2(y1, y1), zd1 = pk2(z1, z1);
    float pp0 = S2 * (x0 * x0 + y0 * y0 + z0 * z0);
    float pp1 = S2 * (x1 * x1 + y1 * y1 + z1 * z1);
    u64 ppd0 = pk2(pp0, pp0), ppd1 = pk2(pp1, pp1);

    float cA0 = 0.f, cA1 = 0.f, cA2 = 0.f, cA3 = 0.f;   // cols 0-7
    float cB0 = 0.f, cB1 = 0.f, cB2 = 0.f, cB3 = 0.f;   // cols 8-15

    #pragma unroll 2
    for (int c = 0; c < NCHUNK; c++) {
        const u64* lp = (const u64*)(s_locp + (c * 4 + tg) * 8);
        u64 m1x = lp[0], m1y = lp[1], m1z = lp[2], bb = lp[3];

        // packed over the bone pair (tg, tg+4)
        u64 d2a = fmax2(xd0, m1x,
                  fmax2(yd0, m1y,
                  fmax2(zd0, m1z, addx2(bb, ppd0))));
        u64 d2b = fmax2(xd1, m1x,
                  fmax2(yd1, m1y,
                  fmax2(zd1, m1z, addx2(bb, ppd1))));

        float dA0, dA1, dB0, dB1;
        upk2(d2a, dA0, dA1);   // (pt g,  bone tg) | (pt g,  bone tg+4)
        upk2(d2b, dB0, dB1);   // (pt g+8, ...)

        u32 a0 = weight_tf32(dA0);   // A[g][tg]
        u32 a1 = weight_tf32(dB0);   // A[g+8][tg]
        u32 a2 = weight_tf32(dA1);   // A[g][tg+4]
        u32 a3 = weight_tf32(dB1);   // A[g+8][tg+4]

        const float2* bp = (const float2*)(s_B + (c * 4 + tg) * 32);
        float2 blo = bp[g];          // (B[8c+tg][g],   B[8c+tg+4][g])
        float2 bhi = bp[g + 8];      // (B[8c+tg][g+8], B[8c+tg+4][g+8])

        mma8(cA0, cA1, cA2, cA3, a0, a1, a2, a3,
             __float_as_uint(blo.x), __float_as_uint(blo.y));
        mma8(cB0, cB1, cB2, cB3, a0, a1, a2, a3,
             __float_as_uint(bhi.x), __float_as_uint(bhi.y));
    }

    // ---------------- epilogue ----------------
    float (*ep)[17] = s_ep[warp];
    ep[g][2 * tg + 0] = cA0;  ep[g][2 * tg + 1] = cA1;
    ep[g + 8][2 * tg + 0] = cA2;  ep[g + 8][2 * tg + 1] = cA3;
    ep[g][8 + 2 * tg + 0] = cB0;  ep[g][8 + 2 * tg + 1] = cB1;
    ep[g + 8][8 + 2 * tg + 0] = cB2;  ep[g + 8][8 + 2 * tg + 1] = cB3;
    __syncwarp();

    if (lane < 16) {
        int pi = pbase + lane;
        if (pi < n) {
            const float* dd = ep[lane];
            float x = xyz[3 * pi], y = xyz[3 * pi + 1], z = xyz[3 * pi + 2];
            float inv;
            asm("rcp.approx.f32 %0, %1;" : "=f"(inv) : "f"(dd[12]));
            out[3 * pi + 0] =
                x + fmaf(dd[0], x, fmaf(dd[1], y, fmaf(dd[2], z, dd[3]))) * inv;
            out[3 * pi + 1] =
                y + fmaf(dd[4], x, fmaf(dd[5], y, fmaf(dd[6], z, dd[7]))) * inv;
            out[3 * pi + 2] =
                z + fmaf(dd[8], x, fmaf(dd[9], y, fmaf(dd[10], z, dd[11]))) * inv;
        }
    }
}

extern "C" void kernel_launch(void* const* d_in, const int* in_sizes, int n_in,
                              void* d_out, int out_size) {
    const float* xyz  = (const float*)d_in[0];   // [N, 3]
    const float* locs = (const float*)d_in[1];   // [512, 3]
    const float* bt   = (const float*)d_in[2];   // [64, 512, 9]
    const int*   tidx = (const int*)d_in[3];     // scalar

    int n = in_sizes[0] / 3;

    int blocks = (n + 63) / 64;
    skin_mma_kernel<<<blocks, 128>>>(xyz, locs, bt, tidx, (float*)d_out, n);
}

// round 12
// speedup vs baseline: 1.5518x; 1.5518x over previous
#include <cuda_runtime.h>
#include <cuda_bf16.h>

#define K_BONES 512
#define NCHUNK  (K_BONES / 8)          // 64 chunks of 8 bones
#define SCALE   28.853900817779268f    // SIGMA * log2(e), SIGMA = 20

typedef unsigned long long u64;
typedef unsigned int u32;

// ---- packed f32x2 helpers (sm_100a) ---------------------------------------
__device__ __forceinline__ u64 pk2(float lo, float hi) {
    u64 r;
    asm("mov.b64 %0, {%1, %2};" : "=l"(r) : "f"(lo), "f"(hi));
    return r;
}
__device__ __forceinline__ void upk2(u64 v, float& lo, float& hi) {
    asm("mov.b64 {%0, %1}, %2;" : "=f"(lo), "=f"(hi) : "l"(v));
}
__device__ __forceinline__ u64 addx2(u64 a, u64 b) {
    u64 r;
    asm("add.rn.f32x2 %0, %1, %2;" : "=l"(r) : "l"(a), "l"(b));
    return r;
}
__device__ __forceinline__ u64 fmax2(u64 a, u64 b, u64 c) {
    u64 r;
    asm("fma.rn.f32x2 %0, %1, %2, %3;" : "=l"(r) : "l"(a), "l"(b), "l"(c));
    return r;
}

// e = ex2(-sqrt(max(d2,0))) -> tf32 bits
__device__ __forceinline__ u32 weight_tf32(float d2) {
    d2 = fmaxf(d2, 0.0f);
    float r, e;
    asm("sqrt.approx.f32 %0, %1;" : "=f"(r) : "f"(d2));
    asm("ex2.approx.f32 %0, %1;" : "=f"(e) : "f"(-r));
    u32 t;
    asm("cvt.rna.tf32.f32 %0, %1;" : "=r"(t) : "f"(e));
    return t;
}

__device__ __forceinline__ u32 tf32_of(float v) {
    u32 t;
    asm("cvt.rna.tf32.f32 %0, %1;" : "=r"(t) : "f"(v));
    return t;
}

// m16n8k8 row.col tf32 MMA, C += A*B
__device__ __forceinline__ void mma8(float& c0, float& c1, float& c2, float& c3,
                                     u32 a0, u32 a1, u32 a2, u32 a3,
                                     u32 b0, u32 b1) {
    asm("mma.sync.aligned.m16n8k8.row.col.f32.tf32.tf32.f32 "
        "{%0,%1,%2,%3}, {%4,%5,%6,%7}, {%8,%9}, {%0,%1,%2,%3};"
        : "+f"(c0), "+f"(c1), "+f"(c2), "+f"(c3)
        : "r"(a0), "r"(a1), "r"(a2), "r"(a3), "r"(b0), "r"(b1));
}

// ---------------------------------------------------------------------------
// Fused tf32-MMA skinning kernel, round-12 fix: B fragments stored in
// PER-LANE order so mainloop B loads are bank-conflict-free.
//   s_B layout: float2 slot [c*64 + lane]      = (B[8c+tg][g],   B[8c+tg+4][g])
//               float2 slot [c*64 + 32 + lane] = (B[8c+tg][g+8], B[8c+tg+4][g+8])
//   (lane = g*4+tg). Load address = lane*8B: each 16-lane phase covers all
//   32 banks exactly once -> minimal 2 wavefronts per LDS.64.
// B matrix [512 x 16] tf32 = delta rows [R-I | t] + ones column (col 12):
// the MMA produces both the blended delta AND the softmax denominator.
// Epilogue: out = p + (D . (x,y,z,1)) / s.
// ---------------------------------------------------------------------------
__global__ __launch_bounds__(128, 5)
void skin_mma_kernel(const float* __restrict__ xyz,
                     const float* __restrict__ bone_locs,
                     const float* __restrict__ bone_transf,
                     const int* __restrict__ tidx_p,
                     float* __restrict__ out, int n) {
    __shared__ float s_locp[NCHUNK * 4 * 8];        // 8 KB
    __shared__ float s_B[NCHUNK * 64 * 2];          // 32 KB (tf32 bits as float)
    __shared__ float s_ep[4][16][17];               // 4.25 KB epilogue scratch

    // ---------------- inline bone prep ----------------
    {
        int t = tidx_p[0];
        float S2 = SCALE * SCALE;
        for (int k = threadIdx.x; k < K_BONES; k += 128) {
            const float* p = bone_transf + ((long long)t * K_BONES + k) * 9;

            float a1x = p[0], a2x = p[1];
            float a1y = p[2], a2y = p[3];
            float a1z = p[4], a2z = p[5];

            float n1 = sqrtf(a1x * a1x + a1y * a1y + a1z * a1z) + 1e-12f;
            float b1x = a1x / n1, b1y = a1y / n1, b1z = a1z / n1;

            float d = b1x * a2x + b1y * a2y + b1z * a2z;
            float cx = a2x - d * b1x, cy = a2y - d * b1y, cz = a2z - d * b1z;
            float n2 = sqrtf(cx * cx + cy * cy + cz * cz) + 1e-12f;
            float b2x = cx / n2, b2y = cy / n2, b2z = cz / n2;

            float b3x = b1y * b2z - b1z * b2y;
            float b3y = b1z * b2x - b1x * b2z;
            float b3z = b1x * b2y - b1y * b2x;

            float bx = bone_locs[3 * k + 0];
            float by = bone_locs[3 * k + 1];
            float bz = bone_locs[3 * k + 2];

            int c = k >> 3, w = k & 7, tg = w & 3, half = w >> 2;

            float* lp = s_locp + (c * 4 + tg) * 8;
            lp[0 * 2 + half] = -2.0f * S2 * bx;
            lp[1 * 2 + half] = -2.0f * S2 * by;
            lp[2 * 2 + half] = -2.0f * S2 * bz;
            lp[3 * 2 + half] = S2 * (bx * bx + by * by + bz * bz);

            // delta-form B row: [R - I | t] + ones column (col 12)
            float Brow[16] = {b1x - 1.0f, b2x, b3x, p[6],
                              b1y, b2y - 1.0f, b3y, p[7],
                              b1z, b2z, b3z - 1.0f, p[8],
                              1.0f, 0.0f, 0.0f, 0.0f};
            // scatter into per-lane fragment order
            #pragma unroll
            for (int j = 0; j < 16; j++) {
                int g = j & 7;
                int hi = j >> 3;                    // 0: blo, 1: bhi
                int slot = c * 64 + hi * 32 + g * 4 + tg;
                s_B[slot * 2 + half] = __uint_as_float(tf32_of(Brow[j]));
            }
        }
    }
    __syncthreads();

    // ---------------- mainloop ----------------
    int lane = threadIdx.x & 31;
    int warp = threadIdx.x >> 5;
    int g = lane >> 2;          // point-group 0..7
    int tg = lane & 3;          // bone-thread 0..3
    int pbase = blockIdx.x * 64 + warp * 16;

    int i0 = pbase + g;
    int i1 = i0 + 8;
    int j0 = i0 < n ? i0 : (n - 1);
    int j1 = i1 < n ? i1 : (n - 1);
    float x0 = xyz[3 * j0], y0 = xyz[3 * j0 + 1], z0 = xyz[3 * j0 + 2];
    float x1 = xyz[3 * j1], y1 = xyz[3 * j1 + 1], z1 = xyz[3 * j1 + 2];

    float S2 = SCALE * SCALE;
    u64 xd0 = pk2(x0, x0), yd0 = pk2(y0, y0), zd0 = pk2(z0, z0);
    u64 xd1 = pk2(x1, x1), yd1 = pk2(y1, y1), zd1 = pk2(z1, z1);
    float pp0 = S2 * (x0 * x0 + y0 * y0 + z0 * z0);
    float pp1 = S2 * (x1 * x1 + y1 * y1 + z1 * z1);
    u64 ppd0 = pk2(pp0, pp0), ppd1 = pk2(pp1, pp1);

    float cA0 = 0.f, cA1 = 0.f, cA2 = 0.f, cA3 = 0.f;   // cols 0-7
    float cB0 = 0.f, cB1 = 0.f, cB2 = 0.f, cB3 = 0.f;   // cols 8-15

    #pragma unroll 2
    for (int c = 0; c < NCHUNK; c++) {
        const u64* lp = (const u64*)(s_locp + (c * 4 + tg) * 8);
        u64 m1x = lp[0], m1y = lp[1], m1z = lp[2], bb = lp[3];

        // packed over the bone pair (tg, tg+4)
        u64 d2a = fmax2(xd0, m1x,
                  fmax2(yd0, m1y,
                  fmax2(zd0, m1z, addx2(bb, ppd0))));
        u64 d2b = fmax2(xd1, m1x,
                  fmax2(yd1, m1y,
                  fmax2(zd1, m1z, addx2(bb, ppd1))));

        float dA0, dA1, dB0, dB1;
        upk2(d2a, dA0, dA1);   // (pt g,  bone tg) | (pt g,  bone tg+4)
        upk2(d2b, dB0, dB1);   // (pt g+8, ...)

        u32 a0 = weight_tf32(dA0);   // A[g][tg]
        u32 a1 = weight_tf32(dB0);   // A[g+8][tg]
        u32 a2 = weight_tf32(dA1);   // A[g][tg+4]
        u32 a3 = weight_tf32(dB1);   // A[g+8][tg+4]

        // conflict-free per-lane fragment loads
        const float2* bp = (const float2*)s_B + c * 64;
        float2 blo = bp[lane];
        float2 bhi = bp[32 + lane];

        mma8(cA0, cA1, cA2, cA3, a0, a1, a2, a3,
             __float_as_uint(blo.x), __float_as_uint(blo.y));
        mma8(cB0, cB1, cB2, cB3, a0, a1, a2, a3,
             __float_as_uint(bhi.x), __float_as_uint(bhi.y));
    }

    // ---------------- epilogue ----------------
    float (*ep)[17] = s_ep[warp];
    ep[g][2 * tg + 0] = cA0;  ep[g][2 * tg + 1] = cA1;
    ep[g + 8][2 * tg + 0] = cA2;  ep[g + 8][2 * tg + 1] = cA3;
    ep[g][8 + 2 * tg + 0] = cB0;  ep[g][8 + 2 * tg + 1] = cB1;
    ep[g + 8][8 + 2 * tg + 0] = cB2;  ep[g + 8][8 + 2 * tg + 1] = cB3;
    __syncwarp();

    if (lane < 16) {
        int pi = pbase + lane;
        if (pi < n) {
            const float* dd = ep[lane];
            float x = xyz[3 * pi], y = xyz[3 * pi + 1], z = xyz[3 * pi + 2];
            float inv;
            asm("rcp.approx.f32 %0, %1;" : "=f"(inv) : "f"(dd[12]));
            out[3 * pi + 0] =
                x + fmaf(dd[0], x, fmaf(dd[1], y, fmaf(dd[2], z, dd[3]))) * inv;
            out[3 * pi + 1] =
                y + fmaf(dd[4], x, fmaf(dd[5], y, fmaf(dd[6], z, dd[7]))) * inv;
            out[3 * pi + 2] =
                z + fmaf(dd[8], x, fmaf(dd[9], y, fmaf(dd[10], z, dd[11]))) * inv;
        }
    }
}

extern "C" void kernel_launch(void* const* d_in, const int* in_sizes, int n_in,
                              void* d_out, int out_size) {
    const float* xyz  = (const float*)d_in[0];   // [N, 3]
    const float* locs = (const float*)d_in[1];   // [512, 3]
    const float* bt   = (const float*)d_in[2];   // [64, 512, 9]
    const int*   tidx = (const int*)d_in[3];     // scalar

    int n = in_sizes[0] / 3;

    int blocks = (n + 63) / 64;
    skin_mma_kernel<<<blocks, 128>>>(xyz, locs, bt, tidx, (float*)d_out, n);
}

// round 13
// speedup vs baseline: 1.8752x; 1.2084x over previous
#include <cuda_runtime.h>
#include <cuda_bf16.h>

#define K_BONES 512
#define NCHUNK  (K_BONES / 8)          // 64 chunks of 8 bones
#define SCALE   28.853900817779268f    // SIGMA * log2(e), SIGMA = 20

typedef unsigned long long u64;
typedef unsigned int u32;

// ---- packed f32x2 helpers (sm_100a) ---------------------------------------
__device__ __forceinline__ u64 pk2(float lo, float hi) {
    u64 r;
    asm("mov.b64 %0, {%1, %2};" : "=l"(r) : "f"(lo), "f"(hi));
    return r;
}
__device__ __forceinline__ void upk2(u64 v, float& lo, float& hi) {
    asm("mov.b64 {%0, %1}, %2;" : "=f"(lo), "=f"(hi) : "l"(v));
}
__device__ __forceinline__ u64 addx2(u64 a, u64 b) {
    u64 r;
    asm("add.rn.f32x2 %0, %1, %2;" : "=l"(r) : "l"(a), "l"(b));
    return r;
}
__device__ __forceinline__ u64 fmax2(u64 a, u64 b, u64 c) {
    u64 r;
    asm("fma.rn.f32x2 %0, %1, %2, %3;" : "=l"(r) : "l"(a), "l"(b), "l"(c));
    return r;
}

// e = ex2(-sqrt(max(d2,0))) as raw f32 bits (tf32 mma reads bits[31:13];
// truncation vs rounding is <=5e-4 relative -- inside the accepted budget)
__device__ __forceinline__ u32 weight_bits(float d2) {
    d2 = fmaxf(d2, 0.0f);
    float r, e;
    asm("sqrt.approx.f32 %0, %1;" : "=f"(r) : "f"(d2));
    asm("ex2.approx.f32 %0, %1;" : "=f"(e) : "f"(-r));
    return __float_as_uint(e);
}

__device__ __forceinline__ u32 tf32_of(float v) {
    u32 t;
    asm("cvt.rna.tf32.f32 %0, %1;" : "=r"(t) : "f"(v));
    return t;
}

// m16n8k8 row.col tf32 MMA, C += A*B
__device__ __forceinline__ void mma8(float& c0, float& c1, float& c2, float& c3,
                                     u32 a0, u32 a1, u32 a2, u32 a3,
                                     u32 b0, u32 b1) {
    asm("mma.sync.aligned.m16n8k8.row.col.f32.tf32.tf32.f32 "
        "{%0,%1,%2,%3}, {%4,%5,%6,%7}, {%8,%9}, {%0,%1,%2,%3};"
        : "+f"(c0), "+f"(c1), "+f"(c2), "+f"(c3)
        : "r"(a0), "r"(a1), "r"(a2), "r"(a3), "r"(b0), "r"(b1));
}

// ---------------------------------------------------------------------------
// Round-13: TWO M-tiles per warp (32 points). Per chunk, the loc-pair loads
// and the conflict-free per-lane B-fragment loads are SHARED by both tiles,
// halving smem wavefronts per point-bone (the round-12 binder at L1=64%).
// B matrix [512 x 16] tf32 = delta rows [R-I | t] + ones col (12): MMA gives
// blended delta + softmax denominator. out = p + (D.(x,y,z,1))/s.
// ---------------------------------------------------------------------------
__global__ __launch_bounds__(128, 5)
void skin_mma_kernel(const float* __restrict__ xyz,
                     const float* __restrict__ bone_locs,
                     const float* __restrict__ bone_transf,
                     const int* __restrict__ tidx_p,
                     float* __restrict__ out, int n) {
    __shared__ float s_locp[NCHUNK * 4 * 8];        // 8 KB
    __shared__ float s_B[NCHUNK * 64 * 2];          // 32 KB (tf32 bits as float)
    __shared__ float s_ep[4][16][17];               // 4.25 KB, reused per tile

    // ---------------- inline bone prep ----------------
    {
        int t = tidx_p[0];
        float S2 = SCALE * SCALE;
        for (int k = threadIdx.x; k < K_BONES; k += 128) {
            const float* p = bone_transf + ((long long)t * K_BONES + k) * 9;

            float a1x = p[0], a2x = p[1];
            float a1y = p[2], a2y = p[3];
            float a1z = p[4], a2z = p[5];

            float n1 = sqrtf(a1x * a1x + a1y * a1y + a1z * a1z) + 1e-12f;
            float b1x = a1x / n1, b1y = a1y / n1, b1z = a1z / n1;

            float d = b1x * a2x + b1y * a2y + b1z * a2z;
            float cx = a2x - d * b1x, cy = a2y - d * b1y, cz = a2z - d * b1z;
            float n2 = sqrtf(cx * cx + cy * cy + cz * cz) + 1e-12f;
            float b2x = cx / n2, b2y = cy / n2, b2z = cz / n2;

            float b3x = b1y * b2z - b1z * b2y;
            float b3y = b1z * b2x - b1x * b2z;
            float b3z = b1x * b2y - b1y * b2x;

            float bx = bone_locs[3 * k + 0];
            float by = bone_locs[3 * k + 1];
            float bz = bone_locs[3 * k + 2];

            int c = k >> 3, w = k & 7, tg = w & 3, half = w >> 2;

            float* lp = s_locp + (c * 4 + tg) * 8;
            lp[0 * 2 + half] = -2.0f * S2 * bx;
            lp[1 * 2 + half] = -2.0f * S2 * by;
            lp[2 * 2 + half] = -2.0f * S2 * bz;
            lp[3 * 2 + half] = S2 * (bx * bx + by * by + bz * bz);

            float Brow[16] = {b1x - 1.0f, b2x, b3x, p[6],
                              b1y, b2y - 1.0f, b3y, p[7],
                              b1z, b2z, b3z - 1.0f, p[8],
                              1.0f, 0.0f, 0.0f, 0.0f};
            #pragma unroll
            for (int j = 0; j < 16; j++) {
                int g = j & 7;
                int hi = j >> 3;
                int slot = c * 64 + hi * 32 + g * 4 + tg;
                s_B[slot * 2 + half] = __uint_as_float(tf32_of(Brow[j]));
            }
        }
    }
    __syncthreads();

    // ---------------- mainloop ----------------
    int lane = threadIdx.x & 31;
    int warp = threadIdx.x >> 5;
    int g = lane >> 2;          // point-group 0..7
    int tg = lane & 3;          // bone-thread 0..3
    int pbase = blockIdx.x * 128 + warp * 32;

    // tile0 points: pbase+g, pbase+8+g; tile1: pbase+16+g, pbase+24+g
    int i0 = pbase + g,      i1 = i0 + 8;
    int i2 = pbase + 16 + g, i3 = i2 + 8;
    int j0 = i0 < n ? i0 : (n - 1);
    int j1 = i1 < n ? i1 : (n - 1);
    int j2 = i2 < n ? i2 : (n - 1);
    int j3 = i3 < n ? i3 : (n - 1);
    float x0 = xyz[3 * j0], y0 = xyz[3 * j0 + 1], z0 = xyz[3 * j0 + 2];
    float x1 = xyz[3 * j1], y1 = xyz[3 * j1 + 1], z1 = xyz[3 * j1 + 2];
    float x2 = xyz[3 * j2], y2 = xyz[3 * j2 + 1], z2 = xyz[3 * j2 + 2];
    float x3 = xyz[3 * j3], y3 = xyz[3 * j3 + 1], z3 = xyz[3 * j3 + 2];

    float S2 = SCALE * SCALE;
    u64 xd0 = pk2(x0, x0), yd0 = pk2(y0, y0), zd0 = pk2(z0, z0);
    u64 xd1 = pk2(x1, x1), yd1 = pk2(y1, y1), zd1 = pk2(z1, z1);
    u64 xd2 = pk2(x2, x2), yd2 = pk2(y2, y2), zd2 = pk2(z2, z2);
    u64 xd3 = pk2(x3, x3), yd3 = pk2(y3, y3), zd3 = pk2(z3, z3);
    u64 ppd0 = pk2(S2 * (x0*x0 + y0*y0 + z0*z0), S2 * (x0*x0 + y0*y0 + z0*z0));
    u64 ppd1 = pk2(S2 * (x1*x1 + y1*y1 + z1*z1), S2 * (x1*x1 + y1*y1 + z1*z1));
    u64 ppd2 = pk2(S2 * (x2*x2 + y2*y2 + z2*z2), S2 * (x2*x2 + y2*y2 + z2*z2));
    u64 ppd3 = pk2(S2 * (x3*x3 + y3*y3 + z3*z3), S2 * (x3*x3 + y3*y3 + z3*z3));

    float cA0=0.f, cA1=0.f, cA2=0.f, cA3=0.f;   // tile0 cols 0-7
    float cB0=0.f, cB1=0.f, cB2=0.f, cB3=0.f;   // tile0 cols 8-15
    float dA0=0.f, dA1=0.f, dA2=0.f, dA3=0.f;   // tile1 cols 0-7
    float dB0=0.f, dB1=0.f, dB2=0.f, dB3=0.f;   // tile1 cols 8-15

    #pragma unroll 2
    for (int c = 0; c < NCHUNK; c++) {
        const u64* lp = (const u64*)(s_locp + (c * 4 + tg) * 8);
        u64 m1x = lp[0], m1y = lp[1], m1z = lp[2], bb = lp[3];

        u64 q0 = fmax2(xd0, m1x, fmax2(yd0, m1y, fmax2(zd0, m1z, addx2(bb, ppd0))));
        u64 q1 = fmax2(xd1, m1x, fmax2(yd1, m1y, fmax2(zd1, m1z, addx2(bb, ppd1))));
        u64 q2 = fmax2(xd2, m1x, fmax2(yd2, m1y, fmax2(zd2, m1z, addx2(bb, ppd2))));
        u64 q3 = fmax2(xd3, m1x, fmax2(yd3, m1y, fmax2(zd3, m1z, addx2(bb, ppd3))));

        float dA_0, dA_1, dB_0, dB_1, dC_0, dC_1, dD_0, dD_1;
        upk2(q0, dA_0, dA_1);
        upk2(q1, dB_0, dB_1);
        upk2(q2, dC_0, dC_1);
        upk2(q3, dD_0, dD_1);

        u32 a0 = weight_bits(dA_0);   // tile0: A[g][tg]
        u32 a1 = weight_bits(dB_0);   //        A[g+8][tg]
        u32 a2 = weight_bits(dA_1);   //        A[g][tg+4]
        u32 a3 = weight_bits(dB_1);   //        A[g+8][tg+4]
        u32 e0 = weight_bits(dC_0);   // tile1
        u32 e1 = weight_bits(dD_0);
        u32 e2 = weight_bits(dC_1);
        u32 e3 = weight_bits(dD_1);

        const float2* bp = (const float2*)s_B + c * 64;
        float2 blo = bp[lane];
        float2 bhi = bp[32 + lane];
        u32 b0 = __float_as_uint(blo.x), b1 = __float_as_uint(blo.y);
        u32 b2 = __float_as_uint(bhi.x), b3 = __float_as_uint(bhi.y);

        mma8(cA0, cA1, cA2, cA3, a0, a1, a2, a3, b0, b1);
        mma8(cB0, cB1, cB2, cB3, a0, a1, a2, a3, b2, b3);
        mma8(dA0, dA1, dA2, dA3, e0, e1, e2, e3, b0, b1);
        mma8(dB0, dB1, dB2, dB3, e0, e1, e2, e3, b2, b3);
    }

    // ---------------- epilogue (two passes over shared scratch) -------------
    float (*ep)[17] = s_ep[warp];

    ep[g][2*tg+0] = cA0;      ep[g][2*tg+1] = cA1;
    ep[g+8][2*tg+0] = cA2;    ep[g+8][2*tg+1] = cA3;
    ep[g][8+2*tg+0] = cB0;    ep[g][8+2*tg+1] = cB1;
    ep[g+8][8+2*tg+0] = cB2;  ep[g+8][8+2*tg+1] = cB3;
    __syncwarp();
    if (lane < 16) {
        int pi = pbase + lane;
        if (pi < n) {
            const float* dd = ep[lane];
            float x = xyz[3*pi], y = xyz[3*pi+1], z = xyz[3*pi+2];
            float inv;
            asm("rcp.approx.f32 %0, %1;" : "=f"(inv) : "f"(dd[12]));
            out[3*pi+0] = x + fmaf(dd[0], x, fmaf(dd[1], y, fmaf(dd[2], z, dd[3]))) * inv;
            out[3*pi+1] = y + fmaf(dd[4], x, fmaf(dd[5], y, fmaf(dd[6], z, dd[7]))) * inv;
            out[3*pi+2] = z + fmaf(dd[8], x, fmaf(dd[9], y, fmaf(dd[10], z, dd[11]))) * inv;
        }
    }
    __syncwarp();

    ep[g][2*tg+0] = dA0;      ep[g][2*tg+1] = dA1;
    ep[g+8][2*tg+0] = dA2;    ep[g+8][2*tg+1] = dA3;
    ep[g][8+2*tg+0] = dB0;    ep[g][8+2*tg+1] = dB1;
    ep[g+8][8+2*tg+0] = dB2;  ep[g+8][8+2*tg+1] = dB3;
    __syncwarp();
    if (lane < 16) {
        int pi = pbase + 16 + lane;
        if (pi < n) {
            const float* dd = ep[lane];
            float x = xyz[3*pi], y = xyz[3*pi+1], z = xyz[3*pi+2];
            float inv;
            asm("rcp.approx.f32 %0, %1;" : "=f"(inv) : "f"(dd[12]));
            out[3*pi+0] = x + fmaf(dd[0], x, fmaf(dd[1], y, fmaf(dd[2], z, dd[3]))) * inv;
            out[3*pi+1] = y + fmaf(dd[4], x, fmaf(dd[5], y, fmaf(dd[6], z, dd[7]))) * inv;
            out[3*pi+2] = z + fmaf(dd[8], x, fmaf(dd[9], y, fmaf(dd[10], z, dd[11]))) * inv;
        }
    }
}

extern "C" void kernel_launch(void* const* d_in, const int* in_sizes, int n_in,
                              void* d_out, int out_size) {
    const float* xyz  = (const float*)d_in[0];   // [N, 3]
    const float* locs = (const float*)d_in[1];   // [512, 3]
    const float* bt   = (const float*)d_in[2];   // [64, 512, 9]
    const int*   tidx = (const int*)d_in[3];     // scalar

    int n = in_sizes[0] / 3;

    int blocks = (n + 127) / 128;
    skin_mma_kernel<<<blocks, 128>>>(xyz, locs, bt, tidx, (float*)d_out, n);
}

// round 14
// speedup vs baseline: 1.8923x; 1.0091x over previous
#include <cuda_runtime.h>
#include <cuda_fp16.h>

#define K_BONES 512
#define NCHUNK  (K_BONES / 16)         // 32 chunks of 16 bones
#define SCALE   28.853900817779268f    // SIGMA * log2(e), SIGMA = 20

typedef unsigned long long u64;
typedef unsigned int u32;

// ---- packed f32x2 helpers (sm_100a) ---------------------------------------
__device__ __forceinline__ u64 pk2(float lo, float hi) {
    u64 r;
    asm("mov.b64 %0, {%1, %2};" : "=l"(r) : "f"(lo), "f"(hi));
    return r;
}
__device__ __forceinline__ void upk2(u64 v, float& lo, float& hi) {
    asm("mov.b64 {%0, %1}, %2;" : "=f"(lo), "=f"(hi) : "l"(v));
}
__device__ __forceinline__ u64 addx2(u64 a, u64 b) {
    u64 r;
    asm("add.rn.f32x2 %0, %1, %2;" : "=l"(r) : "l"(a), "l"(b));
    return r;
}
__device__ __forceinline__ u64 fmax2(u64 a, u64 b, u64 c) {
    u64 r;
    asm("fma.rn.f32x2 %0, %1, %2, %3;" : "=l"(r) : "l"(a), "l"(b), "l"(c));
    return r;
}

// weight pair for one point vs an ADJACENT bone pair: f32 sqrt/ex2 chain,
// packed into one f16x2 A-fragment register (lo = first bone).
__device__ __forceinline__ u32 wpair(u64 d2pair) {
    float da, db;
    upk2(d2pair, da, db);
    da = fmaxf(da, 0.0f);
    db = fmaxf(db, 0.0f);
    float ra, rb, ea, eb;
    asm("sqrt.approx.f32 %0, %1;" : "=f"(ra) : "f"(da));
    asm("sqrt.approx.f32 %0, %1;" : "=f"(rb) : "f"(db));
    asm("ex2.approx.f32 %0, %1;" : "=f"(ea) : "f"(-ra));
    asm("ex2.approx.f32 %0, %1;" : "=f"(eb) : "f"(-rb));
    __half2 h = __floats2half2_rn(ea, eb);    // .x (lo) = ea
    return *reinterpret_cast<u32*>(&h);
}

// m16n8k16 row.col f16 MMA, f32 accumulate
__device__ __forceinline__ void mma16(float& c0, float& c1, float& c2, float& c3,
                                      u32 a0, u32 a1, u32 a2, u32 a3,
                                      u32 b0, u32 b1) {
    asm("mma.sync.aligned.m16n8k16.row.col.f32.f16.f16.f32 "
        "{%0,%1,%2,%3}, {%4,%5,%6,%7}, {%8,%9}, {%0,%1,%2,%3};"
        : "+f"(c0), "+f"(c1), "+f"(c2), "+f"(c3)
        : "r"(a0), "r"(a1), "r"(a2), "r"(a3), "r"(b0), "r"(b1));
}

// ---------------------------------------------------------------------------
// Round-14: f16 MMA (m16n8k16). Per chunk of 16 bones, per lane:
//   - locp: bone-pair loc data for pairs tg and tg+4 (broadcast LDS)
//   - s_B: ONE uint4 = the lane's 4 B-fragment f16x2 regs (conflict-free
//     LDS.128), covering both n-halves of the 16 output columns
//   - weights: f32 distance (f32x2 over adjacent bone pairs) -> sqrt/ex2
//     -> __floats2half2_rn packs straight into the A fragment
// B matrix [512 x 16] f16 = delta rows [R-I | t] + ones col (12): the MMA
// produces blended delta + softmax denominator. out = p + (D.(x,y,z,1))/s.
// Two M-tiles per warp (32 points) share all per-chunk smem traffic.
// smem 28.3 KB -> up to 8 resident blocks (vs 5 at 45 KB).
// ---------------------------------------------------------------------------
__global__ __launch_bounds__(128)
void skin_mma_kernel(const float* __restrict__ xyz,
                     const float* __restrict__ bone_locs,
                     const float* __restrict__ bone_transf,
                     const int* __restrict__ tidx_p,
                     float* __restrict__ out, int n) {
    __shared__ float s_locp[NCHUNK * 8 * 8];        // 8 KB
    __shared__ __half s_B[NCHUNK * 32 * 8];         // 16 KB
    __shared__ float s_ep[4][16][17];               // 4.25 KB, reused per tile

    // ---------------- inline bone prep ----------------
    {
        int t = tidx_p[0];
        float S2 = SCALE * SCALE;
        for (int k = threadIdx.x; k < K_BONES; k += 128) {
            const float* p = bone_transf + ((long long)t * K_BONES + k) * 9;

            float a1x = p[0], a2x = p[1];
            float a1y = p[2], a2y = p[3];
            float a1z = p[4], a2z = p[5];

            float n1 = sqrtf(a1x * a1x + a1y * a1y + a1z * a1z) + 1e-12f;
            float b1x = a1x / n1, b1y = a1y / n1, b1z = a1z / n1;

            float d = b1x * a2x + b1y * a2y + b1z * a2z;
            float cx = a2x - d * b1x, cy = a2y - d * b1y, cz = a2z - d * b1z;
            float n2 = sqrtf(cx * cx + cy * cy + cz * cz) + 1e-12f;
            float b2x = cx / n2, b2y = cy / n2, b2z = cz / n2;

            float b3x = b1y * b2z - b1z * b2y;
            float b3y = b1z * b2x - b1x * b2z;
            float b3z = b1x * b2y - b1y * b2x;

            float bx = bone_locs[3 * k + 0];
            float by = bone_locs[3 * k + 1];
            float bz = bone_locs[3 * k + 2];

            int c = k >> 4, kk = k & 15;
            int pr = kk >> 1, h = kk & 1;           // pair 0..7, lo/hi half
            int tg = pr & 3, which = pr >> 2;       // fragment reg select

            float* lp = s_locp + (c * 8 + pr) * 8;
            lp[0 * 2 + h] = -2.0f * S2 * bx;
            lp[1 * 2 + h] = -2.0f * S2 * by;
            lp[2 * 2 + h] = -2.0f * S2 * bz;
            lp[3 * 2 + h] = S2 * (bx * bx + by * by + bz * bz);

            float Brow[16] = {b1x - 1.0f, b2x, b3x, p[6],
                              b1y, b2y - 1.0f, b3y, p[7],
                              b1z, b2z, b3z - 1.0f, p[8],
                              1.0f, 0.0f, 0.0f, 0.0f};
            #pragma unroll
            for (int j = 0; j < 16; j++) {
                int lane = (j & 7) * 4 + tg;
                int regsel = which + ((j >> 3) << 1);   // b0/b1 | b2/b3
                s_B[((c * 32 + lane) * 4 + regsel) * 2 + h] =
                    __float2half_rn(Brow[j]);
            }
        }
    }
    __syncthreads();

    // ---------------- mainloop ----------------
    int lane = threadIdx.x & 31;
    int warp = threadIdx.x >> 5;
    int g = lane >> 2;          // point-group 0..7
    int tg = lane & 3;          // thread-in-group 0..3
    int pbase = blockIdx.x * 128 + warp * 32;

    int i0 = pbase + g,      i1 = i0 + 8;       // tile0 rows
    int i2 = pbase + 16 + g, i3 = i2 + 8;       // tile1 rows
    int j0 = i0 < n ? i0 : (n - 1);
    int j1 = i1 < n ? i1 : (n - 1);
    int j2 = i2 < n ? i2 : (n - 1);
    int j3 = i3 < n ? i3 : (n - 1);
    float x0 = xyz[3 * j0], y0 = xyz[3 * j0 + 1], z0 = xyz[3 * j0 + 2];
    float x1 = xyz[3 * j1], y1 = xyz[3 * j1 + 1], z1 = xyz[3 * j1 + 2];
    float x2 = xyz[3 * j2], y2 = xyz[3 * j2 + 1], z2 = xyz[3 * j2 + 2];
    float x3 = xyz[3 * j3], y3 = xyz[3 * j3 + 1], z3 = xyz[3 * j3 + 2];

    float S2 = SCALE * SCALE;
    u64 xd0 = pk2(x0, x0), yd0 = pk2(y0, y0), zd0 = pk2(z0, z0);
    u64 xd1 = pk2(x1, x1), yd1 = pk2(y1, y1), zd1 = pk2(z1, z1);
    u64 xd2 = pk2(x2, x2), yd2 = pk2(y2, y2), zd2 = pk2(z2, z2);
    u64 xd3 = pk2(x3, x3), yd3 = pk2(y3, y3), zd3 = pk2(z3, z3);
    float pp0 = S2 * (x0*x0 + y0*y0 + z0*z0);
    float pp1 = S2 * (x1*x1 + y1*y1 + z1*z1);
    float pp2 = S2 * (x2*x2 + y2*y2 + z2*z2);
    float pp3 = S2 * (x3*x3 + y3*y3 + z3*z3);
    u64 ppd0 = pk2(pp0, pp0), ppd1 = pk2(pp1, pp1);
    u64 ppd2 = pk2(pp2, pp2), ppd3 = pk2(pp3, pp3);

    float cA0=0.f, cA1=0.f, cA2=0.f, cA3=0.f;   // tile0 cols 0-7
    float cB0=0.f, cB1=0.f, cB2=0.f, cB3=0.f;   // tile0 cols 8-15
    float dA0=0.f, dA1=0.f, dA2=0.f, dA3=0.f;   // tile1 cols 0-7
    float dB0=0.f, dB1=0.f, dB2=0.f, dB3=0.f;   // tile1 cols 8-15

    #pragma unroll 2
    for (int c = 0; c < NCHUNK; c++) {
        const u64* lpA = (const u64*)(s_locp + (c * 8 + tg) * 8);       // pair tg
        const u64* lpB = (const u64*)(s_locp + (c * 8 + tg + 4) * 8);   // pair tg+4
        u64 mxA = lpA[0], myA = lpA[1], mzA = lpA[2], bbA = lpA[3];
        u64 mxB = lpB[0], myB = lpB[1], mzB = lpB[2], bbB = lpB[3];

        const uint4* bp = (const uint4*)s_B;
        uint4 bf = bp[c * 32 + lane];

        // tile0 weights: points g, g+8 x bone pairs tg (bones 2tg,2tg+1) and tg+4
        u32 a0 = wpair(fmax2(xd0, mxA, fmax2(yd0, myA, fmax2(zd0, mzA, addx2(bbA, ppd0)))));
        u32 a1 = wpair(fmax2(xd1, mxA, fmax2(yd1, myA, fmax2(zd1, mzA, addx2(bbA, ppd1)))));
        u32 a2 = wpair(fmax2(xd0, mxB, fmax2(yd0, myB, fmax2(zd0, mzB, addx2(bbB, ppd0)))));
        u32 a3 = wpair(fmax2(xd1, mxB, fmax2(yd1, myB, fmax2(zd1, mzB, addx2(bbB, ppd1)))));
        mma16(cA0, cA1, cA2, cA3, a0, a1, a2, a3, bf.x, bf.y);
        mma16(cB0, cB1, cB2, cB3, a0, a1, a2, a3, bf.z, bf.w);

        // tile1
        u32 e0 = wpair(fmax2(xd2, mxA, fmax2(yd2, myA, fmax2(zd2, mzA, addx2(bbA, ppd2)))));
        u32 e1 = wpair(fmax2(xd3, mxA, fmax2(yd3, myA, fmax2(zd3, mzA, addx2(bbA, ppd3)))));
        u32 e2 = wpair(fmax2(xd2, mxB, fmax2(yd2, myB, fmax2(zd2, mzB, addx2(bbB, ppd2)))));
        u32 e3 = wpair(fmax2(xd3, mxB, fmax2(yd3, myB, fmax2(zd3, mzB, addx2(bbB, ppd3)))));
        mma16(dA0, dA1, dA2, dA3, e0, e1, e2, e3, bf.x, bf.y);
        mma16(dB0, dB1, dB2, dB3, e0, e1, e2, e3, bf.z, bf.w);
    }

    // ---------------- epilogue (two passes over shared scratch) -------------
    float (*ep)[17] = s_ep[warp];

    ep[g][2*tg+0] = cA0;      ep[g][2*tg+1] = cA1;
    ep[g+8][2*tg+0] = cA2;    ep[g+8][2*tg+1] = cA3;
    ep[g][8+2*tg+0] = cB0;    ep[g][8+2*tg+1] = cB1;
    ep[g+8][8+2*tg+0] = cB2;  ep[g+8][8+2*tg+1] = cB3;
    __syncwarp();
    if (lane < 16) {
        int pi = pbase + lane;
        if (pi < n) {
            const float* dd = ep[lane];
            float x = xyz[3*pi], y = xyz[3*pi+1], z = xyz[3*pi+2];
            float inv;
            asm("rcp.approx.f32 %0, %1;" : "=f"(inv) : "f"(dd[12]));
            out[3*pi+0] = x + fmaf(dd[0], x, fmaf(dd[1], y, fmaf(dd[2], z, dd[3]))) * inv;
            out[3*pi+1] = y + fmaf(dd[4], x, fmaf(dd[5], y, fmaf(dd[6], z, dd[7]))) * inv;
            out[3*pi+2] = z + fmaf(dd[8], x, fmaf(dd[9], y, fmaf(dd[10], z, dd[11]))) * inv;
        }
    }
    __syncwarp();

    ep[g][2*tg+0] = dA0;      ep[g][2*tg+1] = dA1;
    ep[g+8][2*tg+0] = dA2;    ep[g+8][2*tg+1] = dA3;
    ep[g][8+2*tg+0] = dB0;    ep[g][8+2*tg+1] = dB1;
    ep[g+8][8+2*tg+0] = dB2;  ep[g+8][8+2*tg+1] = dB3;
    __syncwarp();
    if (lane < 16) {
        int pi = pbase + 16 + lane;
        if (pi < n) {
            const float* dd = ep[lane];
            float x = xyz[3*pi], y = xyz[3*pi+1], z = xyz[3*pi+2];
            float inv;
            asm("rcp.approx.f32 %0, %1;" : "=f"(inv) : "f"(dd[12]));
            out[3*pi+0] = x + fmaf(dd[0], x, fmaf(dd[1], y, fmaf(dd[2], z, dd[3]))) * inv;
            out[3*pi+1] = y + fmaf(dd[4], x, fmaf(dd[5], y, fmaf(dd[6], z, dd[7]))) * inv;
            out[3*pi+2] = z + fmaf(dd[8], x, fmaf(dd[9], y, fmaf(dd[10], z, dd[11]))) * inv;
        }
    }
}

extern "C" void kernel_launch(void* const* d_in, const int* in_sizes, int n_in,
                              void* d_out, int out_size) {
    const float* xyz  = (const float*)d_in[0];   // [N, 3]
    const float* locs = (const float*)d_in[1];   // [512, 3]
    const float* bt   = (const float*)d_in[2];   // [64, 512, 9]
    const int*   tidx = (const int*)d_in[3];     // scalar

    int n = in_sizes[0] / 3;

    int blocks = (n + 127) / 128;
    skin_mma_kernel<<<blocks, 128>>>(xyz, locs, bt, tidx, (float*)d_out, n);
}

// round 15
// speedup vs baseline: 2.0087x; 1.0616x over previous
#include <cuda_runtime.h>
#include <cuda_fp16.h>

#define K_BONES 512
#define NCHUNK  (K_BONES / 16)         // 32 chunks of 16 bones
#define SCALE   28.853900817779268f    // SIGMA * log2(e), SIGMA = 20

typedef unsigned long long u64;
typedef unsigned int u32;

// ---- packed f32x2 helpers (sm_100a) ---------------------------------------
__device__ __forceinline__ u64 pk2(float lo, float hi) {
    u64 r;
    asm("mov.b64 %0, {%1, %2};" : "=l"(r) : "f"(lo), "f"(hi));
    return r;
}
__device__ __forceinline__ void upk2(u64 v, float& lo, float& hi) {
    asm("mov.b64 {%0, %1}, %2;" : "=f"(lo), "=f"(hi) : "l"(v));
}
__device__ __forceinline__ u64 addx2(u64 a, u64 b) {
    u64 r;
    asm("add.rn.f32x2 %0, %1, %2;" : "=l"(r) : "l"(a), "l"(b));
    return r;
}
__device__ __forceinline__ u64 fmax2(u64 a, u64 b, u64 c) {
    u64 r;
    asm("fma.rn.f32x2 %0, %1, %2, %3;" : "=l"(r) : "l"(a), "l"(b), "l"(c));
    return r;
}

// Weight pair for one point vs an ADJACENT bone pair -> one f16x2 A-fragment
// register. Clamp is folded into the MUFU operand (|d2|); the two sqrt
// results are packed once, sign-flipped with one XOR, and a SINGLE
// ex2.approx.f16x2 produces both weights (3 MUFU total, was 4 + 2 FMNMX).
__device__ __forceinline__ u32 wpair(u64 d2pair) {
    float da, db;
    upk2(d2pair, da, db);
    float ra, rb;
    asm("sqrt.approx.f32 %0, %1;" : "=f"(ra) : "f"(fabsf(da)));
    asm("sqrt.approx.f32 %0, %1;" : "=f"(rb) : "f"(fabsf(db)));
    u32 h;   // f16x2: hi = rb, lo = ra  (lo must be the first bone)
    asm("cvt.rn.f16x2.f32 %0, %1, %2;" : "=r"(h) : "f"(rb), "f"(ra));
    u32 e;
    asm("ex2.approx.f16x2 %0, %1;" : "=r"(e) : "r"(h ^ 0x80008000u));
    return e;
}

// m16n8k16 row.col f16 MMA, f32 accumulate
__device__ __forceinline__ void mma16(float& c0, float& c1, float& c2, float& c3,
                                      u32 a0, u32 a1, u32 a2, u32 a3,
                                      u32 b0, u32 b1) {
    asm("mma.sync.aligned.m16n8k16.row.col.f32.f16.f16.f32 "
        "{%0,%1,%2,%3}, {%4,%5,%6,%7}, {%8,%9}, {%0,%1,%2,%3};"
        : "+f"(c0), "+f"(c1), "+f"(c2), "+f"(c3)
        : "r"(a0), "r"(a1), "r"(a2), "r"(a3), "r"(b0), "r"(b1));
}

// ---------------------------------------------------------------------------
// f16 MMA (m16n8k16) skinning, round-15: stripped weight path.
// Per chunk of 16 bones: broadcast loc-pair LDS + ONE conflict-free uint4
// B-fragment LDS.128 per lane, 8 wpairs (3 MUFU each), 4 MMAs covering
// 32 points x 16 bones. B matrix [512 x 16] f16 = delta rows [R-I | t] +
// ones col (12): the MMA yields blended delta + softmax denominator.
// out = p + (D.(x,y,z,1))/s.
// ---------------------------------------------------------------------------
__global__ __launch_bounds__(128)
void skin_mma_kernel(const float* __restrict__ xyz,
                     const float* __restrict__ bone_locs,
                     const float* __restrict__ bone_transf,
                     const int* __restrict__ tidx_p,
                     float* __restrict__ out, int n) {
    __shared__ float s_locp[NCHUNK * 8 * 8];        // 8 KB
    __shared__ __half s_B[NCHUNK * 32 * 8];         // 16 KB
    __shared__ float s_ep[4][16][17];               // 4.25 KB, reused per tile

    // ---------------- inline bone prep ----------------
    {
        int t = tidx_p[0];
        float S2 = SCALE * SCALE;
        for (int k = threadIdx.x; k < K_BONES; k += 128) {
            const float* p = bone_transf + ((long long)t * K_BONES + k) * 9;

            float a1x = p[0], a2x = p[1];
            float a1y = p[2], a2y = p[3];
            float a1z = p[4], a2z = p[5];

            float n1 = sqrtf(a1x * a1x + a1y * a1y + a1z * a1z) + 1e-12f;
            float b1x = a1x / n1, b1y = a1y / n1, b1z = a1z / n1;

            float d = b1x * a2x + b1y * a2y + b1z * a2z;
            float cx = a2x - d * b1x, cy = a2y - d * b1y, cz = a2z - d * b1z;
            float n2 = sqrtf(cx * cx + cy * cy + cz * cz) + 1e-12f;
            float b2x = cx / n2, b2y = cy / n2, b2z = cz / n2;

            float b3x = b1y * b2z - b1z * b2y;
            float b3y = b1z * b2x - b1x * b2z;
            float b3z = b1x * b2y - b1y * b2x;

            float bx = bone_locs[3 * k + 0];
            float by = bone_locs[3 * k + 1];
            float bz = bone_locs[3 * k + 2];

            int c = k >> 4, kk = k & 15;
            int pr = kk >> 1, h = kk & 1;           // pair 0..7, lo/hi half
            int tg = pr & 3, which = pr >> 2;       // fragment reg select

            float* lp = s_locp + (c * 8 + pr) * 8;
            lp[0 * 2 + h] = -2.0f * S2 * bx;
            lp[1 * 2 + h] = -2.0f * S2 * by;
            lp[2 * 2 + h] = -2.0f * S2 * bz;
            lp[3 * 2 + h] = S2 * (bx * bx + by * by + bz * bz);

            float Brow[16] = {b1x - 1.0f, b2x, b3x, p[6],
                              b1y, b2y - 1.0f, b3y, p[7],
                              b1z, b2z, b3z - 1.0f, p[8],
                              1.0f, 0.0f, 0.0f, 0.0f};
            #pragma unroll
            for (int j = 0; j < 16; j++) {
                int lane = (j & 7) * 4 + tg;
                int regsel = which + ((j >> 3) << 1);   // b0/b1 | b2/b3
                s_B[((c * 32 + lane) * 4 + regsel) * 2 + h] =
                    __float2half_rn(Brow[j]);
            }
        }
    }
    __syncthreads();

    // ---------------- mainloop ----------------
    int lane = threadIdx.x & 31;
    int warp = threadIdx.x >> 5;
    int g = lane >> 2;          // point-group 0..7
    int tg = lane & 3;          // thread-in-group 0..3
    int pbase = blockIdx.x * 128 + warp * 32;

    int i0 = pbase + g,      i1 = i0 + 8;       // tile0 rows
    int i2 = pbase + 16 + g, i3 = i2 + 8;       // tile1 rows
    int j0 = i0 < n ? i0 : (n - 1);
    int j1 = i1 < n ? i1 : (n - 1);
    int j2 = i2 < n ? i2 : (n - 1);
    int j3 = i3 < n ? i3 : (n - 1);
    float x0 = xyz[3 * j0], y0 = xyz[3 * j0 + 1], z0 = xyz[3 * j0 + 2];
    float x1 = xyz[3 * j1], y1 = xyz[3 * j1 + 1], z1 = xyz[3 * j1 + 2];
    float x2 = xyz[3 * j2], y2 = xyz[3 * j2 + 1], z2 = xyz[3 * j2 + 2];
    float x3 = xyz[3 * j3], y3 = xyz[3 * j3 + 1], z3 = xyz[3 * j3 + 2];

    float S2 = SCALE * SCALE;
    u64 xd0 = pk2(x0, x0), yd0 = pk2(y0, y0), zd0 = pk2(z0, z0);
    u64 xd1 = pk2(x1, x1), yd1 = pk2(y1, y1), zd1 = pk2(z1, z1);
    u64 xd2 = pk2(x2, x2), yd2 = pk2(y2, y2), zd2 = pk2(z2, z2);
    u64 xd3 = pk2(x3, x3), yd3 = pk2(y3, y3), zd3 = pk2(z3, z3);
    float pp0 = S2 * (x0*x0 + y0*y0 + z0*z0);
    float pp1 = S2 * (x1*x1 + y1*y1 + z1*z1);
    float pp2 = S2 * (x2*x2 + y2*y2 + z2*z2);
    float pp3 = S2 * (x3*x3 + y3*y3 + z3*z3);
    u64 ppd0 = pk2(pp0, pp0), ppd1 = pk2(pp1, pp1);
    u64 ppd2 = pk2(pp2, pp2), ppd3 = pk2(pp3, pp3);

    float cA0=0.f, cA1=0.f, cA2=0.f, cA3=0.f;   // tile0 cols 0-7
    float cB0=0.f, cB1=0.f, cB2=0.f, cB3=0.f;   // tile0 cols 8-15
    float dA0=0.f, dA1=0.f, dA2=0.f, dA3=0.f;   // tile1 cols 0-7
    float dB0=0.f, dB1=0.f, dB2=0.f, dB3=0.f;   // tile1 cols 8-15

    #pragma unroll 4
    for (int c = 0; c < NCHUNK; c++) {
        const u64* lpA = (const u64*)(s_locp + (c * 8 + tg) * 8);       // pair tg
        const u64* lpB = (const u64*)(s_locp + (c * 8 + tg + 4) * 8);   // pair tg+4
        u64 mxA = lpA[0], myA = lpA[1], mzA = lpA[2], bbA = lpA[3];
        u64 mxB = lpB[0], myB = lpB[1], mzB = lpB[2], bbB = lpB[3];

        const uint4* bp = (const uint4*)s_B;
        uint4 bf = bp[c * 32 + lane];

        // tile0 weights: points g, g+8 x bone pairs tg (bones 2tg,2tg+1), tg+4
        u32 a0 = wpair(fmax2(xd0, mxA, fmax2(yd0, myA, fmax2(zd0, mzA, addx2(bbA, ppd0)))));
        u32 a1 = wpair(fmax2(xd1, mxA, fmax2(yd1, myA, fmax2(zd1, mzA, addx2(bbA, ppd1)))));
        u32 a2 = wpair(fmax2(xd0, mxB, fmax2(yd0, myB, fmax2(zd0, mzB, addx2(bbB, ppd0)))));
        u32 a3 = wpair(fmax2(xd1, mxB, fmax2(yd1, myB, fmax2(zd1, mzB, addx2(bbB, ppd1)))));
        mma16(cA0, cA1, cA2, cA3, a0, a1, a2, a3, bf.x, bf.y);
        mma16(cB0, cB1, cB2, cB3, a0, a1, a2, a3, bf.z, bf.w);

        // tile1
        u32 e0 = wpair(fmax2(xd2, mxA, fmax2(yd2, myA, fmax2(zd2, mzA, addx2(bbA, ppd2)))));
        u32 e1 = wpair(fmax2(xd3, mxA, fmax2(yd3, myA, fmax2(zd3, mzA, addx2(bbA, ppd3)))));
        u32 e2 = wpair(fmax2(xd2, mxB, fmax2(yd2, myB, fmax2(zd2, mzB, addx2(bbB, ppd2)))));
        u32 e3 = wpair(fmax2(xd3, mxB, fmax2(yd3, myB, fmax2(zd3, mzB, addx2(bbB, ppd3)))));
        mma16(dA0, dA1, dA2, dA3, e0, e1, e2, e3, bf.x, bf.y);
        mma16(dB0, dB1, dB2, dB3, e0, e1, e2, e3, bf.z, bf.w);
    }

    // ---------------- epilogue (two passes over shared scratch) -------------
    float (*ep)[17] = s_ep[warp];

    ep[g][2*tg+0] = cA0;      ep[g][2*tg+1] = cA1;
    ep[g+8][2*tg+0] = cA2;    ep[g+8][2*tg+1] = cA3;
    ep[g][8+2*tg+0] = cB0;    ep[g][8+2*tg+1] = cB1;
    ep[g+8][8+2*tg+0] = cB2;  ep[g+8][8+2*tg+1] = cB3;
    __syncwarp();
    if (lane < 16) {
        int pi = pbase + lane;
        if (pi < n) {
            const float* dd = ep[lane];
            float x = xyz[3*pi], y = xyz[3*pi+1], z = xyz[3*pi+2];
            float inv;
            asm("rcp.approx.f32 %0, %1;" : "=f"(inv) : "f"(dd[12]));
            out[3*pi+0] = x + fmaf(dd[0], x, fmaf(dd[1], y, fmaf(dd[2], z, dd[3]))) * inv;
            out[3*pi+1] = y + fmaf(dd[4], x, fmaf(dd[5], y, fmaf(dd[6], z, dd[7]))) * inv;
            out[3*pi+2] = z + fmaf(dd[8], x, fmaf(dd[9], y, fmaf(dd[10], z, dd[11]))) * inv;
        }
    }
    __syncwarp();

    ep[g][2*tg+0] = dA0;      ep[g][2*tg+1] = dA1;
    ep[g+8][2*tg+0] = dA2;    ep[g+8][2*tg+1] = dA3;
    ep[g][8+2*tg+0] = dB0;    ep[g][8+2*tg+1] = dB1;
    ep[g+8][8+2*tg+0] = dB2;  ep[g+8][8+2*tg+1] = dB3;
    __syncwarp();
    if (lane < 16) {
        int pi = pbase + 16 + lane;
        if (pi < n) {
            const float* dd = ep[lane];
            float x = xyz[3*pi], y = xyz[3*pi+1], z = xyz[3*pi+2];
            float inv;
            asm("rcp.approx.f32 %0, %1;" : "=f"(inv) : "f"(dd[12]));
            out[3*pi+0] = x + fmaf(dd[0], x, fmaf(dd[1], y, fmaf(dd[2], z, dd[3]))) * inv;
            out[3*pi+1] = y + fmaf(dd[4], x, fmaf(dd[5], y, fmaf(dd[6], z, dd[7]))) * inv;
            out[3*pi+2] = z + fmaf(dd[8], x, fmaf(dd[9], y, fmaf(dd[10], z, dd[11]))) * inv;
        }
    }
}

extern "C" void kernel_launch(void* const* d_in, const int* in_sizes, int n_in,
                              void* d_out, int out_size) {
    const float* xyz  = (const float*)d_in[0];   // [N, 3]
    const float* locs = (const float*)d_in[1];   // [512, 3]
    const float* bt   = (const float*)d_in[2];   // [64, 512, 9]
    const int*   tidx = (const int*)d_in[3];     // scalar

    int n = in_sizes[0] / 3;

    int blocks = (n + 127) / 128;
    skin_mma_kernel<<<blocks, 128>>>(xyz, locs, bt, tidx, (float*)d_out, n);
}

// round 16
// speedup vs baseline: 2.0696x; 1.0303x over previous
#include <cuda_runtime.h>
#include <cuda_fp16.h>

#define K_BONES 512
#define NCHUNK  (K_BONES / 16)         // 32 chunks of 16 bones
#define SCALE   28.853900817779268f    // SIGMA * log2(e), SIGMA = 20

typedef unsigned long long u64;
typedef unsigned int u32;

// ---- packed f32x2 helpers (sm_100a) ---------------------------------------
__device__ __forceinline__ u64 pk2(float lo, float hi) {
    u64 r;
    asm("mov.b64 %0, {%1, %2};" : "=l"(r) : "f"(lo), "f"(hi));
    return r;
}
__device__ __forceinline__ void upk2(u64 v, float& lo, float& hi) {
    asm("mov.b64 {%0, %1}, %2;" : "=f"(lo), "=f"(hi) : "l"(v));
}
__device__ __forceinline__ u64 addx2(u64 a, u64 b) {
    u64 r;
    asm("add.rn.f32x2 %0, %1, %2;" : "=l"(r) : "l"(a), "l"(b));
    return r;
}
__device__ __forceinline__ u64 fmax2(u64 a, u64 b, u64 c) {
    u64 r;
    asm("fma.rn.f32x2 %0, %1, %2, %3;" : "=l"(r) : "l"(a), "l"(b), "l"(c));
    return r;
}
__device__ __forceinline__ float rsqrt_approx(float v) {
    float r;
    asm("rsqrt.approx.f32 %0, %1;" : "=f"(r) : "f"(v));
    return r;
}

// Weight pair for one point vs an ADJACENT bone pair -> one f16x2 A-fragment
// register. Clamp folds into the MUFU operand (|d2|); one pack, one XOR
// sign-flip, one ex2.approx.f16x2 for the pair (3 MUFU total).
__device__ __forceinline__ u32 wpair(u64 d2pair) {
    float da, db;
    upk2(d2pair, da, db);
    float ra, rb;
    asm("sqrt.approx.f32 %0, %1;" : "=f"(ra) : "f"(fabsf(da)));
    asm("sqrt.approx.f32 %0, %1;" : "=f"(rb) : "f"(fabsf(db)));
    u32 h;   // f16x2: hi = rb, lo = ra  (lo must be the first bone)
    asm("cvt.rn.f16x2.f32 %0, %1, %2;" : "=r"(h) : "f"(rb), "f"(ra));
    u32 e;
    asm("ex2.approx.f16x2 %0, %1;" : "=r"(e) : "r"(h ^ 0x80008000u));
    return e;
}

// m16n8k16 row.col f16 MMA, f32 accumulate
__device__ __forceinline__ void mma16(float& c0, float& c1, float& c2, float& c3,
                                      u32 a0, u32 a1, u32 a2, u32 a3,
                                      u32 b0, u32 b1) {
    asm("mma.sync.aligned.m16n8k16.row.col.f32.f16.f16.f32 "
        "{%0,%1,%2,%3}, {%4,%5,%6,%7}, {%8,%9}, {%0,%1,%2,%3};"
        : "+f"(c0), "+f"(c1), "+f"(c2), "+f"(c3)
        : "r"(a0), "r"(a1), "r"(a2), "r"(a3), "r"(b0), "r"(b1));
}

// ---------------------------------------------------------------------------
// f16 MMA (m16n8k16) skinning, round-16: approx-math prep (rsqrt.approx +
// mul, no fdiv/sqrtf — prep was ~8-10% of issued instructions), guaranteed
// LDS.128 loc-pair loads (ulonglong2), unroll 8.
// Per chunk of 16 bones: 2x2 LDS.128 broadcast loc loads + ONE conflict-free
// uint4 B-fragment LDS.128 per lane, 8 wpairs (3 MUFU each), 4 MMAs covering
// 32 points x 16 bones. B [512 x 16] f16 = delta rows [R-I | t] + ones col:
// MMA yields blended delta + softmax denominator. out = p + (D.(x,y,z,1))/s.
// ---------------------------------------------------------------------------
__global__ __launch_bounds__(128)
void skin_mma_kernel(const float* __restrict__ xyz,
                     const float* __restrict__ bone_locs,
                     const float* __restrict__ bone_transf,
                     const int* __restrict__ tidx_p,
                     float* __restrict__ out, int n) {
    __shared__ float s_locp[NCHUNK * 8 * 8];        // 8 KB
    __shared__ __half s_B[NCHUNK * 32 * 8];         // 16 KB
    __shared__ float s_ep[4][16][17];               // 4.25 KB, reused per tile

    // ---------------- inline bone prep (approx math) ----------------
    {
        int t = tidx_p[0];
        float S2 = SCALE * SCALE;
        for (int k = threadIdx.x; k < K_BONES; k += 128) {
            const float* p = bone_transf + ((long long)t * K_BONES + k) * 9;

            float a1x = p[0], a2x = p[1];
            float a1y = p[2], a2y = p[3];
            float a1z = p[4], a2z = p[5];

            float q1 = a1x * a1x + a1y * a1y + a1z * a1z;
            float in1 = rsqrt_approx(q1);
            float b1x = a1x * in1, b1y = a1y * in1, b1z = a1z * in1;

            float d = b1x * a2x + b1y * a2y + b1z * a2z;
            float cx = a2x - d * b1x, cy = a2y - d * b1y, cz = a2z - d * b1z;
            float q2 = cx * cx + cy * cy + cz * cz;
            float in2 = rsqrt_approx(q2);
            float b2x = cx * in2, b2y = cy * in2, b2z = cz * in2;

            float b3x = b1y * b2z - b1z * b2y;
            float b3y = b1z * b2x - b1x * b2z;
            float b3z = b1x * b2y - b1y * b2x;

            float bx = bone_locs[3 * k + 0];
            float by = bone_locs[3 * k + 1];
            float bz = bone_locs[3 * k + 2];

            int c = k >> 4, kk = k & 15;
            int pr = kk >> 1, h = kk & 1;           // pair 0..7, lo/hi half
            int tg = pr & 3, which = pr >> 2;       // fragment reg select

            float* lp = s_locp + (c * 8 + pr) * 8;
            lp[0 * 2 + h] = -2.0f * S2 * bx;
            lp[1 * 2 + h] = -2.0f * S2 * by;
            lp[2 * 2 + h] = -2.0f * S2 * bz;
            lp[3 * 2 + h] = S2 * (bx * bx + by * by + bz * bz);

            float Brow[16] = {b1x - 1.0f, b2x, b3x, p[6],
                              b1y, b2y - 1.0f, b3y, p[7],
                              b1z, b2z, b3z - 1.0f, p[8],
                              1.0f, 0.0f, 0.0f, 0.0f};
            #pragma unroll
            for (int j = 0; j < 16; j++) {
                int lane = (j & 7) * 4 + tg;
                int regsel = which + ((j >> 3) << 1);   // b0/b1 | b2/b3
                s_B[((c * 32 + lane) * 4 + regsel) * 2 + h] =
                    __float2half_rn(Brow[j]);
            }
        }
    }
    __syncthreads();

    // ---------------- mainloop ----------------
    int lane = threadIdx.x & 31;
    int warp = threadIdx.x >> 5;
    int g = lane >> 2;          // point-group 0..7
    int tg = lane & 3;          // thread-in-group 0..3
    int pbase = blockIdx.x * 128 + warp * 32;

    int i0 = pbase + g,      i1 = i0 + 8;       // tile0 rows
    int i2 = pbase + 16 + g, i3 = i2 + 8;       // tile1 rows
    int j0 = i0 < n ? i0 : (n - 1);
    int j1 = i1 < n ? i1 : (n - 1);
    int j2 = i2 < n ? i2 : (n - 1);
    int j3 = i3 < n ? i3 : (n - 1);
    float x0 = xyz[3 * j0], y0 = xyz[3 * j0 + 1], z0 = xyz[3 * j0 + 2];
    float x1 = xyz[3 * j1], y1 = xyz[3 * j1 + 1], z1 = xyz[3 * j1 + 2];
    float x2 = xyz[3 * j2], y2 = xyz[3 * j2 + 1], z2 = xyz[3 * j2 + 2];
    float x3 = xyz[3 * j3], y3 = xyz[3 * j3 + 1], z3 = xyz[3 * j3 + 2];

    float S2 = SCALE * SCALE;
    u64 xd0 = pk2(x0, x0), yd0 = pk2(y0, y0), zd0 = pk2(z0, z0);
    u64 xd1 = pk2(x1, x1), yd1 = pk2(y1, y1), zd1 = pk2(z1, z1);
    u64 xd2 = pk2(x2, x2), yd2 = pk2(y2, y2), zd2 = pk2(z2, z2);
    u64 xd3 = pk2(x3, x3), yd3 = pk2(y3, y3), zd3 = pk2(z3, z3);
    float pp0 = S2 * (x0*x0 + y0*y0 + z0*z0);
    float pp1 = S2 * (x1*x1 + y1*y1 + z1*z1);
    float pp2 = S2 * (x2*x2 + y2*y2 + z2*z2);
    float pp3 = S2 * (x3*x3 + y3*y3 + z3*z3);
    u64 ppd0 = pk2(pp0, pp0), ppd1 = pk2(pp1, pp1);
    u64 ppd2 = pk2(pp2, pp2), ppd3 = pk2(pp3, pp3);

    float cA0=0.f, cA1=0.f, cA2=0.f, cA3=0.f;   // tile0 cols 0-7
    float cB0=0.f, cB1=0.f, cB2=0.f, cB3=0.f;   // tile0 cols 8-15
    float dA0=0.f, dA1=0.f, dA2=0.f, dA3=0.f;   // tile1 cols 0-7
    float dB0=0.f, dB1=0.f, dB2=0.f, dB3=0.f;   // tile1 cols 8-15

    #pragma unroll 8
    for (int c = 0; c < NCHUNK; c++) {
        // guaranteed LDS.128: each pair row is one aligned ulonglong2 x2
        const ulonglong2* lpA = (const ulonglong2*)(s_locp + (c * 8 + tg) * 8);
        const ulonglong2* lpB = (const ulonglong2*)(s_locp + (c * 8 + tg + 4) * 8);
        ulonglong2 lA0 = lpA[0], lA1 = lpA[1];
        ulonglong2 lB0 = lpB[0], lB1 = lpB[1];
        u64 mxA = lA0.x, myA = lA0.y, mzA = lA1.x, bbA = lA1.y;
        u64 mxB = lB0.x, myB = lB0.y, mzB = lB1.x, bbB = lB1.y;

        const uint4* bp = (const uint4*)s_B;
        uint4 bf = bp[c * 32 + lane];

        // tile0 weights: points g, g+8 x bone pairs tg (bones 2tg,2tg+1), tg+4
        u32 a0 = wpair(fmax2(xd0, mxA, fmax2(yd0, myA, fmax2(zd0, mzA, addx2(bbA, ppd0)))));
        u32 a1 = wpair(fmax2(xd1, mxA, fmax2(yd1, myA, fmax2(zd1, mzA, addx2(bbA, ppd1)))));
        u32 a2 = wpair(fmax2(xd0, mxB, fmax2(yd0, myB, fmax2(zd0, mzB, addx2(bbB, ppd0)))));
        u32 a3 = wpair(fmax2(xd1, mxB, fmax2(yd1, myB, fmax2(zd1, mzB, addx2(bbB, ppd1)))));
        mma16(cA0, cA1, cA2, cA3, a0, a1, a2, a3, bf.x, bf.y);
        mma16(cB0, cB1, cB2, cB3, a0, a1, a2, a3, bf.z, bf.w);

        // tile1
        u32 e0 = wpair(fmax2(xd2, mxA, fmax2(yd2, myA, fmax2(zd2, mzA, addx2(bbA, ppd2)))));
        u32 e1 = wpair(fmax2(xd3, mxA, fmax2(yd3, myA, fmax2(zd3, mzA, addx2(bbA, ppd3)))));
        u32 e2 = wpair(fmax2(xd2, mxB, fmax2(yd2, myB, fmax2(zd2, mzB, addx2(bbB, ppd2)))));
        u32 e3 = wpair(fmax2(xd3, mxB, fmax2(yd3, myB, fmax2(zd3, mzB, addx2(bbB, ppd3)))));
        mma16(dA0, dA1, dA2, dA3, e0, e1, e2, e3, bf.x, bf.y);
        mma16(dB0, dB1, dB2, dB3, e0, e1, e2, e3, bf.z, bf.w);
    }

    // ---------------- epilogue (two passes over shared scratch) -------------
    float (*ep)[17] = s_ep[warp];

    ep[g][2*tg+0] = cA0;      ep[g][2*tg+1] = cA1;
    ep[g+8][2*tg+0] = cA2;    ep[g+8][2*tg+1] = cA3;
    ep[g][8+2*tg+0] = cB0;    ep[g][8+2*tg+1] = cB1;
    ep[g+8][8+2*tg+0] = cB2;  ep[g+8][8+2*tg+1] = cB3;
    __syncwarp();
    if (lane < 16) {
        int pi = pbase + lane;
        if (pi < n) {
            const float* dd = ep[lane];
            float x = xyz[3*pi], y = xyz[3*pi+1], z = xyz[3*pi+2];
            float inv;
            asm("rcp.approx.f32 %0, %1;" : "=f"(inv) : "f"(dd[12]));
            out[3*pi+0] = x + fmaf(dd[0], x, fmaf(dd[1], y, fmaf(dd[2], z, dd[3]))) * inv;
            out[3*pi+1] = y + fmaf(dd[4], x, fmaf(dd[5], y, fmaf(dd[6], z, dd[7]))) * inv;
            out[3*pi+2] = z + fmaf(dd[8], x, fmaf(dd[9], y, fmaf(dd[10], z, dd[11]))) * inv;
        }
    }
    __syncwarp();

    ep[g][2*tg+0] = dA0;      ep[g][2*tg+1] = dA1;
    ep[g+8][2*tg+0] = dA2;    ep[g+8][2*tg+1] = dA3;
    ep[g][8+2*tg+0] = dB0;    ep[g][8+2*tg+1] = dB1;
    ep[g+8][8+2*tg+0] = dB2;  ep[g+8][8+2*tg+1] = dB3;
    __syncwarp();
    if (lane < 16) {
        int pi = pbase + 16 + lane;
        if (pi < n) {
            const float* dd = ep[lane];
            float x = xyz[3*pi], y = xyz[3*pi+1], z = xyz[3*pi+2];
            float inv;
            asm("rcp.approx.f32 %0, %1;" : "=f"(inv) : "f"(dd[12]));
            out[3*pi+0] = x + fmaf(dd[0], x, fmaf(dd[1], y, fmaf(dd[2], z, dd[3]))) * inv;
            out[3*pi+1] = y + fmaf(dd[4], x, fmaf(dd[5], y, fmaf(dd[6], z, dd[7]))) * inv;
            out[3*pi+2] = z + fmaf(dd[8], x, fmaf(dd[9], y, fmaf(dd[10], z, dd[11]))) * inv;
        }
    }
}

extern "C" void kernel_launch(void* const* d_in, const int* in_sizes, int n_in,
                              void* d_out, int out_size) {
    const float* xyz  = (const float*)d_in[0];   // [N, 3]
    const float* locs = (const float*)d_in[1];   // [512, 3]
    const float* bt   = (const float*)d_in[2];   // [64, 512, 9]
    const int*   tidx = (const int*)d_in[3];     // scalar

    int n = in_sizes[0] / 3;

    int blocks = (n + 127) / 128;
    skin_mma_kernel<<<blocks, 128>>>(xyz, locs, bt, tidx, (float*)d_out, n);
}